// round 2
// baseline (speedup 1.0000x reference)
#include <cuda_runtime.h>
#include <cuda_bf16.h>
#include <cuda_fp8.h>
#include <cstdint>

// Problem dims (fixed by setup_inputs): B=4,S=2048 -> M=8192, H=K=4096, O=N=4096
#define MDIM 8192
#define KDIM 4096
#define NDIM 4096

// ---------------- scratch (static __device__, allocation-free) ----------------
__device__ __nv_bfloat16 g_A[(size_t)MDIM * KDIM];     // e4m3 values of norm*scale, exact in bf16
__device__ __nv_bfloat16 g_Whi[(size_t)NDIM * KDIM];   // bf16 high part of W
__device__ __nv_bfloat16 g_Wlo[(size_t)NDIM * KDIM];   // bf16 low  part of W

// ---------------- helpers ----------------
__device__ __forceinline__ uint32_t smem_u32(const void* p) {
    uint32_t a;
    asm("{ .reg .u64 t; cvta.to.shared.u64 t, %1; cvt.u32.u64 %0, t; }" : "=r"(a) : "l"(p));
    return a;
}
__device__ __forceinline__ void cp_async16(uint32_t dst, const void* src) {
    asm volatile("cp.async.cg.shared.global [%0], [%1], 16;"
                 :: "r"(dst), "l"(__cvta_generic_to_global(src)) : "memory");
}
__device__ __forceinline__ uint32_t sw128(uint32_t off) { return off ^ ((off >> 3) & 0x70); }

__device__ __forceinline__ void ldm_x4(uint32_t* r, uint32_t addr) {
    asm volatile("ldmatrix.sync.aligned.m8n8.x4.shared.b16 {%0,%1,%2,%3}, [%4];"
                 : "=r"(r[0]), "=r"(r[1]), "=r"(r[2]), "=r"(r[3]) : "r"(addr));
}
__device__ __forceinline__ void mma_bf16(float* c, const uint32_t* a, const uint32_t* b) {
    asm volatile(
        "mma.sync.aligned.m16n8k16.row.col.f32.bf16.bf16.f32 "
        "{%0,%1,%2,%3}, {%4,%5,%6,%7}, {%8,%9}, {%0,%1,%2,%3};"
        : "+f"(c[0]), "+f"(c[1]), "+f"(c[2]), "+f"(c[3])
        : "r"(a[0]), "r"(a[1]), "r"(a[2]), "r"(a[3]), "r"(b[0]), "r"(b[1]));
}

// ---------------- prologue kernels ----------------
__global__ void init_kernel(unsigned* amax_u) {
    if (threadIdx.x == 0) *amax_u = 0u;
}

__global__ void __launch_bounds__(256) convert_w_kernel(const float* __restrict__ W) {
    size_t i = ((size_t)blockIdx.x * 256 + threadIdx.x) * 4;
    float4 w = *(const float4*)(W + i);
    __nv_bfloat16 h0 = __float2bfloat16(w.x);
    __nv_bfloat16 h1 = __float2bfloat16(w.y);
    __nv_bfloat16 h2 = __float2bfloat16(w.z);
    __nv_bfloat16 h3 = __float2bfloat16(w.w);
    __nv_bfloat16 l0 = __float2bfloat16(w.x - __bfloat162float(h0));
    __nv_bfloat16 l1 = __float2bfloat16(w.y - __bfloat162float(h1));
    __nv_bfloat16 l2 = __float2bfloat16(w.z - __bfloat162float(h2));
    __nv_bfloat16 l3 = __float2bfloat16(w.w - __bfloat162float(h3));
    __nv_bfloat162* hp = (__nv_bfloat162*)&g_Whi[i];
    __nv_bfloat162* lp = (__nv_bfloat162*)&g_Wlo[i];
    hp[0] = __nv_bfloat162(h0, h1); hp[1] = __nv_bfloat162(h2, h3);
    lp[0] = __nv_bfloat162(l0, l1); lp[1] = __nv_bfloat162(l2, l3);
}

__device__ __forceinline__ float warp_sum(float v) {
    #pragma unroll
    for (int o = 16; o; o >>= 1) v += __shfl_xor_sync(0xFFFFFFFFu, v, o);
    return v;
}
__device__ __forceinline__ float warp_max(float v) {
    #pragma unroll
    for (int o = 16; o; o >>= 1) v = fmaxf(v, __shfl_xor_sync(0xFFFFFFFFu, v, o));
    return v;
}

// fused residual add + RMSNorm + fp8 quant (raw e4m3 value kept; 1/scale folded into epilogue)
__global__ void __launch_bounds__(256) norm_kernel(
    const float* __restrict__ x, const float* __restrict__ r,
    const float* __restrict__ lw, const float* __restrict__ scale_p,
    float* __restrict__ res_out, unsigned* __restrict__ amax_u)
{
    int row = blockIdx.x;
    size_t base = (size_t)row * KDIM;
    const float4* x4 = (const float4*)(x + base);
    const float4* r4 = (const float4*)(r + base);
    float4* ro4 = (float4*)(res_out + base);

    float4 v[4];
    float ss = 0.f;
    #pragma unroll
    for (int j = 0; j < 4; j++) {
        int i = threadIdx.x + j * 256;
        float4 a = x4[i];
        float4 bb = r4[i];
        a.x += bb.x; a.y += bb.y; a.z += bb.z; a.w += bb.w;
        v[j] = a;
        ro4[i] = a;
        ss += a.x * a.x + a.y * a.y + a.z * a.z + a.w * a.w;
    }
    __shared__ float red[8];
    __shared__ float bcast;
    int wid = threadIdx.x >> 5, lid = threadIdx.x & 31;
    float ws = warp_sum(ss);
    if (lid == 0) red[wid] = ws;
    __syncthreads();
    if (wid == 0) {
        float t = (lid < 8) ? red[lid] : 0.f;
        #pragma unroll
        for (int o = 4; o; o >>= 1) t += __shfl_xor_sync(0xFFFFFFFFu, t, o);
        if (lid == 0) bcast = t;
    }
    __syncthreads();
    float rstd = rsqrtf(bcast * (1.0f / KDIM) + 1e-5f);
    float s = __ldg(scale_p);

    float am = 0.f;
    const float4* w4 = (const float4*)lw;
    #pragma unroll
    for (int j = 0; j < 4; j++) {
        int i = threadIdx.x + j * 256;
        float4 wv = w4[i];
        float n0 = v[j].x * rstd * wv.x;
        float n1 = v[j].y * rstd * wv.y;
        float n2 = v[j].z * rstd * wv.z;
        float n3 = v[j].w * rstd * wv.w;
        am = fmaxf(am, fmaxf(fmaxf(fabsf(n0), fabsf(n1)), fmaxf(fabsf(n2), fabsf(n3))));
        float q0 = (float)__nv_fp8_e4m3(fminf(fmaxf(n0 * s, -448.f), 448.f));
        float q1 = (float)__nv_fp8_e4m3(fminf(fmaxf(n1 * s, -448.f), 448.f));
        float q2 = (float)__nv_fp8_e4m3(fminf(fmaxf(n2 * s, -448.f), 448.f));
        float q3 = (float)__nv_fp8_e4m3(fminf(fmaxf(n3 * s, -448.f), 448.f));
        __nv_bfloat162* ap = (__nv_bfloat162*)&g_A[base + (size_t)i * 4];
        ap[0] = __nv_bfloat162(__float2bfloat16(q0), __float2bfloat16(q1)); // exact: e4m3 subset of bf16
        ap[1] = __nv_bfloat162(__float2bfloat16(q2), __float2bfloat16(q3));
    }
    float wm = warp_max(am);
    if (lid == 0) red[wid] = wm;
    __syncthreads();
    if (threadIdx.x == 0) {
        float t = red[0];
        #pragma unroll
        for (int k = 1; k < 8; k++) t = fmaxf(t, red[k]);
        atomicMax(amax_u, __float_as_uint(t)); // all values >= 0: uint order == float order
    }
}

// ---------------- GEMM: out[M,N] = A[M,K] @ (Whi+Wlo)[N,K]^T  (mma.sync bf16) ----------------
#define BK 64
#define GSTAGES 3
#define STAGE_BYTES 49152              // A 16K + Whi 16K + Wlo 16K
#define BH_OFF 16384
#define BL_OFF 32768
#define SMEM_TOTAL (GSTAGES * STAGE_BYTES)   // 147456
#define NITER (KDIM / BK)              // 64

__device__ __forceinline__ void load_stage(uint32_t sb, int buf, int t, int m0, int n0, int tid) {
    uint32_t base = sb + buf * STAGE_BYTES;
    int kk0 = t * BK;
    #pragma unroll
    for (int i = 0; i < 12; i++) {
        int u = tid + i * 256;          // 0..3071
        int mat = u >> 10;              // 0:A 1:Whi 2:Wlo
        int v = u & 1023;
        int row = v >> 3;
        int c = v & 7;                  // 16B chunk in 128B row
        uint32_t dst = base + (mat << 14) + sw128((row << 7) | (c << 4));
        const __nv_bfloat16* src;
        if (mat == 0)      src = g_A   + (size_t)(m0 + row) * KDIM + kk0 + c * 8;
        else if (mat == 1) src = g_Whi + (size_t)(n0 + row) * KDIM + kk0 + c * 8;
        else               src = g_Wlo + (size_t)(n0 + row) * KDIM + kk0 + c * 8;
        cp_async16(dst, src);
    }
}

__global__ void __launch_bounds__(256, 1) gemm_kernel(
    const float* __restrict__ bias, const float* __restrict__ scale_p, float* __restrict__ out)
{
    extern __shared__ __align__(1024) char smem[];
    uint32_t sb = smem_u32(smem);
    int tid = threadIdx.x, wid = tid >> 5, lane = tid & 31;

    // tile rasterization with M-grouping for L2 reuse of W
    constexpr int PN = NDIM / 128, GM = 8;
    int pid = blockIdx.x;
    int group = pid / (GM * PN);
    int m_t = group * GM + (pid % GM);
    int n_t = (pid % (GM * PN)) / GM;
    int m0 = m_t * 128, n0 = n_t * 128;

    int wm0 = (wid & 1) * 64;   // warp computes rows [wm0, wm0+64)
    int wn0 = (wid >> 1) * 32;  // warp computes cols [wn0, wn0+32)

    // ldmatrix lane decomposition
    int mi = lane >> 3;         // matrix index 0..3
    int lr = lane & 7;          // row within 8x8 matrix

    float acc[4][4][4];
    #pragma unroll
    for (int a = 0; a < 4; a++)
        #pragma unroll
        for (int b = 0; b < 4; b++)
            #pragma unroll
            for (int c = 0; c < 4; c++) acc[a][b][c] = 0.f;

    // prologue: prefetch stages 0,1
    #pragma unroll
    for (int t = 0; t < GSTAGES - 1; t++) {
        load_stage(sb, t, t, m0, n0, tid);
        asm volatile("cp.async.commit_group;" ::: "memory");
    }

    for (int s = 0; s < NITER; s++) {
        asm volatile("cp.async.wait_group 1;" ::: "memory");
        __syncthreads();

        int nt = s + GSTAGES - 1;
        if (nt < NITER) load_stage(sb, nt % GSTAGES, nt, m0, n0, tid);
        asm volatile("cp.async.commit_group;" ::: "memory");

        uint32_t bufA = sb + (s % GSTAGES) * STAGE_BYTES;
        #pragma unroll
        for (int ks = 0; ks < 4; ks++) {
            int kk = ks * 16;
            // A fragments: 4 m16 tiles
            uint32_t aF[4][4];
            #pragma unroll
            for (int tm = 0; tm < 4; tm++) {
                int row = wm0 + tm * 16 + (mi & 1) * 8 + lr;
                int kc = kk + (mi >> 1) * 8;
                ldm_x4(aF[tm], bufA + sw128((uint32_t)(row * 128 + kc * 2)));
            }
            // Whi fragments + mma
            {
                uint32_t bF[4][2];
                #pragma unroll
                for (int p = 0; p < 2; p++) {
                    int nrow = wn0 + p * 16 + (mi >> 1) * 8 + lr;
                    int kc = kk + (mi & 1) * 8;
                    uint32_t r[4];
                    ldm_x4(r, bufA + BH_OFF + sw128((uint32_t)(nrow * 128 + kc * 2)));
                    bF[2 * p][0] = r[0]; bF[2 * p][1] = r[1];
                    bF[2 * p + 1][0] = r[2]; bF[2 * p + 1][1] = r[3];
                }
                #pragma unroll
                for (int tm = 0; tm < 4; tm++)
                    #pragma unroll
                    for (int tn = 0; tn < 4; tn++)
                        mma_bf16(acc[tm][tn], aF[tm], bF[tn]);
            }
            // Wlo fragments + mma (same accumulators)
            {
                uint32_t bF[4][2];
                #pragma unroll
                for (int p = 0; p < 2; p++) {
                    int nrow = wn0 + p * 16 + (mi >> 1) * 8 + lr;
                    int kc = kk + (mi & 1) * 8;
                    uint32_t r[4];
                    ldm_x4(r, bufA + BL_OFF + sw128((uint32_t)(nrow * 128 + kc * 2)));
                    bF[2 * p][0] = r[0]; bF[2 * p][1] = r[1];
                    bF[2 * p + 1][0] = r[2]; bF[2 * p + 1][1] = r[3];
                }
                #pragma unroll
                for (int tm = 0; tm < 4; tm++)
                    #pragma unroll
                    for (int tn = 0; tn < 4; tn++)
                        mma_bf16(acc[tm][tn], aF[tm], bF[tn]);
            }
        }
    }

    // ---- epilogue: scale by 1/s, add bias, write fp32 ----
    float inv_s = 1.0f / __ldg(scale_p);
    int g = lane >> 2;
    int c2 = (lane & 3) * 2;
    #pragma unroll
    for (int tm = 0; tm < 4; tm++) {
        #pragma unroll
        for (int tn = 0; tn < 4; tn++) {
            int m = m0 + wm0 + tm * 16 + g;
            int n = n0 + wn0 + tn * 8 + c2;
            float2 bv = *(const float2*)(bias + n);
            float2 o0, o1;
            o0.x = acc[tm][tn][0] * inv_s + bv.x;
            o0.y = acc[tm][tn][1] * inv_s + bv.y;
            o1.x = acc[tm][tn][2] * inv_s + bv.x;
            o1.y = acc[tm][tn][3] * inv_s + bv.y;
            *(float2*)(out + (size_t)m * NDIM + n) = o0;
            *(float2*)(out + (size_t)(m + 8) * NDIM + n) = o1;
        }
    }
}

// ---------------- launch ----------------
extern "C" void kernel_launch(void* const* d_in, const int* in_sizes, int n_in,
                              void* d_out, int out_size) {
    (void)in_sizes; (void)n_in; (void)out_size;
    const float* x     = (const float*)d_in[0];
    const float* res   = (const float*)d_in[1];
    const float* lw    = (const float*)d_in[2];
    const float* W     = (const float*)d_in[3];
    const float* bias  = (const float*)d_in[4];
    const float* scale = (const float*)d_in[5];

    float* out = (float*)d_out;
    float* res_out = out + (size_t)MDIM * NDIM;
    unsigned* amax_u = (unsigned*)(out + 2ull * (size_t)MDIM * NDIM);

    init_kernel<<<1, 32>>>(amax_u);
    convert_w_kernel<<<(NDIM * KDIM) / 1024, 256>>>(W);
    norm_kernel<<<MDIM, 256>>>(x, res, lw, scale, res_out, amax_u);

    cudaFuncSetAttribute(gemm_kernel, cudaFuncAttributeMaxDynamicSharedMemorySize, SMEM_TOTAL);
    gemm_kernel<<<(MDIM / 128) * (NDIM / 128), 256, SMEM_TOTAL>>>(bias, scale, out);
}

// round 3
// speedup vs baseline: 1.8706x; 1.8706x over previous
#include <cuda_runtime.h>
#include <cuda_fp16.h>
#include <cuda_fp8.h>
#include <cstdint>

// Problem dims (fixed by setup_inputs): B=4,S=2048 -> M=8192, H=K=4096, O=N=4096
#define MDIM 8192
#define KDIM 4096
#define NDIM 4096

// ---------------- scratch (static __device__, allocation-free) ----------------
__device__ __half g_A[(size_t)MDIM * KDIM];   // e4m3 values of norm*scale (exact in fp16)
__device__ __half g_W[(size_t)NDIM * KDIM];   // fp16 W

// ---------------- helpers ----------------
__device__ __forceinline__ uint32_t smem_u32(const void* p) {
    uint32_t a;
    asm("{ .reg .u64 t; cvta.to.shared.u64 t, %1; cvt.u32.u64 %0, t; }" : "=r"(a) : "l"(p));
    return a;
}
__device__ __forceinline__ void cp_async16(uint32_t dst, const void* src) {
    asm volatile("cp.async.cg.shared.global [%0], [%1], 16;"
                 :: "r"(dst), "l"(__cvta_generic_to_global(src)) : "memory");
}
__device__ __forceinline__ uint32_t sw128(uint32_t off) { return off ^ ((off >> 3) & 0x70); }

__device__ __forceinline__ void ldm_x4(uint32_t* r, uint32_t addr) {
    asm volatile("ldmatrix.sync.aligned.m8n8.x4.shared.b16 {%0,%1,%2,%3}, [%4];"
                 : "=r"(r[0]), "=r"(r[1]), "=r"(r[2]), "=r"(r[3]) : "r"(addr));
}
__device__ __forceinline__ void mma_f16(float* c, const uint32_t* a, const uint32_t* b) {
    asm volatile(
        "mma.sync.aligned.m16n8k16.row.col.f32.f16.f16.f32 "
        "{%0,%1,%2,%3}, {%4,%5,%6,%7}, {%8,%9}, {%0,%1,%2,%3};"
        : "+f"(c[0]), "+f"(c[1]), "+f"(c[2]), "+f"(c[3])
        : "r"(a[0]), "r"(a[1]), "r"(a[2]), "r"(a[3]), "r"(b[0]), "r"(b[1]));
}

// ---------------- prologue kernels ----------------
__global__ void init_kernel(unsigned* amax_u) {
    if (threadIdx.x == 0) *amax_u = 0u;
}

__global__ void __launch_bounds__(256) convert_w_kernel(const float* __restrict__ W) {
    size_t i = ((size_t)blockIdx.x * 256 + threadIdx.x) * 4;
    float4 w = *(const float4*)(W + i);
    __half2* hp = (__half2*)&g_W[i];
    hp[0] = __half2(__float2half_rn(w.x), __float2half_rn(w.y));
    hp[1] = __half2(__float2half_rn(w.z), __float2half_rn(w.w));
}

__device__ __forceinline__ float warp_sum(float v) {
    #pragma unroll
    for (int o = 16; o; o >>= 1) v += __shfl_xor_sync(0xFFFFFFFFu, v, o);
    return v;
}
__device__ __forceinline__ float warp_max(float v) {
    #pragma unroll
    for (int o = 16; o; o >>= 1) v = fmaxf(v, __shfl_xor_sync(0xFFFFFFFFu, v, o));
    return v;
}

// fused residual add + RMSNorm + fp8 quant (raw e4m3 value kept; 1/scale folded into epilogue)
__global__ void __launch_bounds__(256) norm_kernel(
    const float* __restrict__ x, const float* __restrict__ r,
    const float* __restrict__ lw, const float* __restrict__ scale_p,
    float* __restrict__ res_out, unsigned* __restrict__ amax_u)
{
    int row = blockIdx.x;
    size_t base = (size_t)row * KDIM;
    const float4* x4 = (const float4*)(x + base);
    const float4* r4 = (const float4*)(r + base);
    float4* ro4 = (float4*)(res_out + base);

    float4 v[4];
    float ss = 0.f;
    #pragma unroll
    for (int j = 0; j < 4; j++) {
        int i = threadIdx.x + j * 256;
        float4 a = x4[i];
        float4 bb = r4[i];
        a.x += bb.x; a.y += bb.y; a.z += bb.z; a.w += bb.w;
        v[j] = a;
        ro4[i] = a;
        ss += a.x * a.x + a.y * a.y + a.z * a.z + a.w * a.w;
    }
    __shared__ float red[8];
    __shared__ float bcast;
    int wid = threadIdx.x >> 5, lid = threadIdx.x & 31;
    float ws = warp_sum(ss);
    if (lid == 0) red[wid] = ws;
    __syncthreads();
    if (wid == 0) {
        float t = (lid < 8) ? red[lid] : 0.f;
        #pragma unroll
        for (int o = 4; o; o >>= 1) t += __shfl_xor_sync(0xFFFFFFFFu, t, o);
        if (lid == 0) bcast = t;
    }
    __syncthreads();
    float rstd = rsqrtf(bcast * (1.0f / KDIM) + 1e-5f);
    float s = __ldg(scale_p);

    float am = 0.f;
    const float4* w4 = (const float4*)lw;
    #pragma unroll
    for (int j = 0; j < 4; j++) {
        int i = threadIdx.x + j * 256;
        float4 wv = w4[i];
        float n0 = v[j].x * rstd * wv.x;
        float n1 = v[j].y * rstd * wv.y;
        float n2 = v[j].z * rstd * wv.z;
        float n3 = v[j].w * rstd * wv.w;
        am = fmaxf(am, fmaxf(fmaxf(fabsf(n0), fabsf(n1)), fmaxf(fabsf(n2), fabsf(n3))));
        float q0 = (float)__nv_fp8_e4m3(fminf(fmaxf(n0 * s, -448.f), 448.f));
        float q1 = (float)__nv_fp8_e4m3(fminf(fmaxf(n1 * s, -448.f), 448.f));
        float q2 = (float)__nv_fp8_e4m3(fminf(fmaxf(n2 * s, -448.f), 448.f));
        float q3 = (float)__nv_fp8_e4m3(fminf(fmaxf(n3 * s, -448.f), 448.f));
        __half2* ap = (__half2*)&g_A[base + (size_t)i * 4];
        ap[0] = __half2(__float2half_rn(q0), __float2half_rn(q1)); // exact: e4m3 subset of fp16
        ap[1] = __half2(__float2half_rn(q2), __float2half_rn(q3));
    }
    float wm = warp_max(am);
    if (lid == 0) red[wid] = wm;
    __syncthreads();
    if (threadIdx.x == 0) {
        float t = red[0];
        #pragma unroll
        for (int k = 1; k < 8; k++) t = fmaxf(t, red[k]);
        atomicMax(amax_u, __float_as_uint(t)); // all values >= 0: uint order == float order
    }
}

// ---------------- GEMM: out[M,N] = A[M,K] @ W[N,K]^T  (mma.sync fp16, fp32 accum) ----------------
// CTA tile: 256(M) x 128(N), BK=64, 512 threads (16 warps, 4x4), 4-stage cp.async
#define BM 256
#define BN 128
#define BK 64
#define GSTAGES 4
#define A_BYTES (BM * 128)             // 32768
#define W_OFFB  A_BYTES
#define STAGE_BYTES (A_BYTES + BN * 128)   // 49152
#define SMEM_TOTAL (GSTAGES * STAGE_BYTES) // 196608
#define NITER (KDIM / BK)              // 64

__device__ __forceinline__ void load_stage(uint32_t sb, int buf, int t, int m0, int n0, int tid) {
    uint32_t base = sb + buf * STAGE_BYTES;
    int kk0 = t * BK;
    #pragma unroll
    for (int i = 0; i < 6; i++) {
        int u = tid + i * 512;          // 0..3071 ; 0..2047 = A, 2048..3071 = W
        const __half* src;
        uint32_t dst;
        if (u < 2048) {
            int row = u >> 3, c = u & 7;
            dst = base + sw128((uint32_t)((row << 7) | (c << 4)));
            src = g_A + (size_t)(m0 + row) * KDIM + kk0 + c * 8;
        } else {
            int v = u - 2048;
            int row = v >> 3, c = v & 7;
            dst = base + W_OFFB + sw128((uint32_t)((row << 7) | (c << 4)));
            src = g_W + (size_t)(n0 + row) * KDIM + kk0 + c * 8;
        }
        cp_async16(dst, src);
    }
}

__global__ void __launch_bounds__(512, 1) gemm_kernel(
    const float* __restrict__ bias, const float* __restrict__ scale_p, float* __restrict__ out)
{
    extern __shared__ __align__(1024) char smem[];
    uint32_t sb = smem_u32(smem);
    int tid = threadIdx.x, wid = tid >> 5, lane = tid & 31;

    // tile rasterization with M-grouping for L2 reuse of W
    constexpr int PN = NDIM / BN, GM = 8;          // PN=32
    int pid = blockIdx.x;
    int group = pid / (GM * PN);
    int m_t = group * GM + (pid % GM);
    int n_t = (pid % (GM * PN)) / GM;
    int m0 = m_t * BM, n0 = n_t * BN;

    int wm0 = (wid & 3) * 64;   // warp rows [wm0, wm0+64)
    int wn0 = (wid >> 2) * 32;  // warp cols [wn0, wn0+32)

    int mi = lane >> 3;         // ldmatrix sub-matrix index 0..3
    int lr = lane & 7;          // row within 8x8

    float acc[4][4][4];
    #pragma unroll
    for (int a = 0; a < 4; a++)
        #pragma unroll
        for (int b = 0; b < 4; b++)
            #pragma unroll
            for (int c = 0; c < 4; c++) acc[a][b][c] = 0.f;

    // prologue: prefetch stages 0..2
    #pragma unroll
    for (int t = 0; t < GSTAGES - 1; t++) {
        load_stage(sb, t, t, m0, n0, tid);
        asm volatile("cp.async.commit_group;" ::: "memory");
    }

    for (int s = 0; s < NITER; s++) {
        asm volatile("cp.async.wait_group 2;" ::: "memory");
        __syncthreads();

        int nt = s + GSTAGES - 1;
        if (nt < NITER) load_stage(sb, nt % GSTAGES, nt, m0, n0, tid);
        asm volatile("cp.async.commit_group;" ::: "memory");

        uint32_t buf = sb + (s % GSTAGES) * STAGE_BYTES;
        #pragma unroll
        for (int ks = 0; ks < 4; ks++) {
            int kk = ks * 16;
            // A fragments: 4 m16 tiles
            uint32_t aF[4][4];
            #pragma unroll
            for (int tm = 0; tm < 4; tm++) {
                int row = wm0 + tm * 16 + (mi & 1) * 8 + lr;
                int kc = kk + (mi >> 1) * 8;
                ldm_x4(aF[tm], buf + sw128((uint32_t)(row * 128 + kc * 2)));
            }
            // W fragments: 4 n8 tiles (two ldmatrix.x4)
            uint32_t bF[4][2];
            #pragma unroll
            for (int p = 0; p < 2; p++) {
                int nrow = wn0 + p * 16 + (mi >> 1) * 8 + lr;
                int kc = kk + (mi & 1) * 8;
                uint32_t r[4];
                ldm_x4(r, buf + W_OFFB + sw128((uint32_t)(nrow * 128 + kc * 2)));
                bF[2 * p][0] = r[0]; bF[2 * p][1] = r[1];
                bF[2 * p + 1][0] = r[2]; bF[2 * p + 1][1] = r[3];
            }
            #pragma unroll
            for (int tm = 0; tm < 4; tm++)
                #pragma unroll
                for (int tn = 0; tn < 4; tn++)
                    mma_f16(acc[tm][tn], aF[tm], bF[tn]);
        }
    }

    // ---- epilogue: scale by 1/s, add bias, write fp32 ----
    float inv_s = 1.0f / __ldg(scale_p);
    int g = lane >> 2;
    int c2 = (lane & 3) * 2;
    #pragma unroll
    for (int tm = 0; tm < 4; tm++) {
        #pragma unroll
        for (int tn = 0; tn < 4; tn++) {
            int m = m0 + wm0 + tm * 16 + g;
            int n = n0 + wn0 + tn * 8 + c2;
            float2 bv = *(const float2*)(bias + n);
            float2 o0, o1;
            o0.x = acc[tm][tn][0] * inv_s + bv.x;
            o0.y = acc[tm][tn][1] * inv_s + bv.y;
            o1.x = acc[tm][tn][2] * inv_s + bv.x;
            o1.y = acc[tm][tn][3] * inv_s + bv.y;
            *(float2*)(out + (size_t)m * NDIM + n) = o0;
            *(float2*)(out + (size_t)(m + 8) * NDIM + n) = o1;
        }
    }
}

// ---------------- launch ----------------
extern "C" void kernel_launch(void* const* d_in, const int* in_sizes, int n_in,
                              void* d_out, int out_size) {
    (void)in_sizes; (void)n_in; (void)out_size;
    const float* x     = (const float*)d_in[0];
    const float* res   = (const float*)d_in[1];
    const float* lw    = (const float*)d_in[2];
    const float* W     = (const float*)d_in[3];
    const float* bias  = (const float*)d_in[4];
    const float* scale = (const float*)d_in[5];

    float* out = (float*)d_out;
    float* res_out = out + (size_t)MDIM * NDIM;
    unsigned* amax_u = (unsigned*)(out + 2ull * (size_t)MDIM * NDIM);

    init_kernel<<<1, 32>>>(amax_u);
    convert_w_kernel<<<(NDIM * KDIM) / 1024, 256>>>(W);
    norm_kernel<<<MDIM, 256>>>(x, res, lw, scale, res_out, amax_u);

    cudaFuncSetAttribute(gemm_kernel, cudaFuncAttributeMaxDynamicSharedMemorySize, SMEM_TOTAL);
    gemm_kernel<<<(MDIM / BM) * (NDIM / BN), 512, SMEM_TOTAL>>>(bias, scale, out);
}

// round 4
// speedup vs baseline: 1.9953x; 1.0667x over previous
#include <cuda_runtime.h>
#include <cuda_fp16.h>
#include <cuda_fp8.h>
#include <cstdint>

// Problem dims (fixed by setup_inputs): B=4,S=2048 -> M=8192, H=K=4096, O=N=4096
#define MDIM 8192
#define KDIM 4096
#define NDIM 4096

// ---------------- scratch (static __device__, allocation-free) ----------------
__device__ __half g_A[(size_t)MDIM * KDIM];   // e4m3 values of norm*scale (exact in fp16)
__device__ __half g_W[(size_t)NDIM * KDIM];   // fp16 W

// ---------------- helpers ----------------
__device__ __forceinline__ uint32_t smem_u32(const void* p) {
    uint32_t a;
    asm("{ .reg .u64 t; cvta.to.shared.u64 t, %1; cvt.u32.u64 %0, t; }" : "=r"(a) : "l"(p));
    return a;
}
__device__ __forceinline__ void cp_async16(uint32_t dst, const void* src) {
    asm volatile("cp.async.cg.shared.global [%0], [%1], 16;"
                 :: "r"(dst), "l"(__cvta_generic_to_global(src)) : "memory");
}
__device__ __forceinline__ uint32_t sw128(uint32_t off) { return off ^ ((off >> 3) & 0x70); }

__device__ __forceinline__ void ldm_x4(uint32_t* r, uint32_t addr) {
    asm volatile("ldmatrix.sync.aligned.m8n8.x4.shared.b16 {%0,%1,%2,%3}, [%4];"
                 : "=r"(r[0]), "=r"(r[1]), "=r"(r[2]), "=r"(r[3]) : "r"(addr));
}
__device__ __forceinline__ void mma_f16(float* c, const uint32_t* a, const uint32_t* b) {
    asm volatile(
        "mma.sync.aligned.m16n8k16.row.col.f32.f16.f16.f32 "
        "{%0,%1,%2,%3}, {%4,%5,%6,%7}, {%8,%9}, {%0,%1,%2,%3};"
        : "+f"(c[0]), "+f"(c[1]), "+f"(c[2]), "+f"(c[3])
        : "r"(a[0]), "r"(a[1]), "r"(a[2]), "r"(a[3]), "r"(b[0]), "r"(b[1]));
}

// ---------------- prologue kernels ----------------
__global__ void init_kernel(unsigned* amax_u) {
    if (threadIdx.x == 0) *amax_u = 0u;
}

__global__ void __launch_bounds__(256) convert_w_kernel(const float* __restrict__ W) {
    size_t i = ((size_t)blockIdx.x * 256 + threadIdx.x) * 4;
    float4 w = *(const float4*)(W + i);
    __half2* hp = (__half2*)&g_W[i];
    hp[0] = __half2(__float2half_rn(w.x), __float2half_rn(w.y));
    hp[1] = __half2(__float2half_rn(w.z), __float2half_rn(w.w));
}

__device__ __forceinline__ float warp_sum(float v) {
    #pragma unroll
    for (int o = 16; o; o >>= 1) v += __shfl_xor_sync(0xFFFFFFFFu, v, o);
    return v;
}
__device__ __forceinline__ float warp_max(float v) {
    #pragma unroll
    for (int o = 16; o; o >>= 1) v = fmaxf(v, __shfl_xor_sync(0xFFFFFFFFu, v, o));
    return v;
}

// fused residual add + RMSNorm + fp8 quant (raw e4m3 value kept; 1/scale folded into epilogue)
__global__ void __launch_bounds__(256) norm_kernel(
    const float* __restrict__ x, const float* __restrict__ r,
    const float* __restrict__ lw, const float* __restrict__ scale_p,
    float* __restrict__ res_out, unsigned* __restrict__ amax_u)
{
    int row = blockIdx.x;
    size_t base = (size_t)row * KDIM;
    const float4* x4 = (const float4*)(x + base);
    const float4* r4 = (const float4*)(r + base);
    float4* ro4 = (float4*)(res_out + base);

    float4 v[4];
    float ss = 0.f;
    #pragma unroll
    for (int j = 0; j < 4; j++) {
        int i = threadIdx.x + j * 256;
        float4 a = x4[i];
        float4 bb = r4[i];
        a.x += bb.x; a.y += bb.y; a.z += bb.z; a.w += bb.w;
        v[j] = a;
        ro4[i] = a;
        ss += a.x * a.x + a.y * a.y + a.z * a.z + a.w * a.w;
    }
    __shared__ float red[8];
    __shared__ float bcast;
    int wid = threadIdx.x >> 5, lid = threadIdx.x & 31;
    float ws = warp_sum(ss);
    if (lid == 0) red[wid] = ws;
    __syncthreads();
    if (wid == 0) {
        float t = (lid < 8) ? red[lid] : 0.f;
        #pragma unroll
        for (int o = 4; o; o >>= 1) t += __shfl_xor_sync(0xFFFFFFFFu, t, o);
        if (lid == 0) bcast = t;
    }
    __syncthreads();
    float rstd = rsqrtf(bcast * (1.0f / KDIM) + 1e-5f);
    float s = __ldg(scale_p);

    float am = 0.f;
    const float4* w4 = (const float4*)lw;
    #pragma unroll
    for (int j = 0; j < 4; j++) {
        int i = threadIdx.x + j * 256;
        float4 wv = w4[i];
        float n0 = v[j].x * rstd * wv.x;
        float n1 = v[j].y * rstd * wv.y;
        float n2 = v[j].z * rstd * wv.z;
        float n3 = v[j].w * rstd * wv.w;
        am = fmaxf(am, fmaxf(fmaxf(fabsf(n0), fabsf(n1)), fmaxf(fabsf(n2), fabsf(n3))));
        float q0 = (float)__nv_fp8_e4m3(fminf(fmaxf(n0 * s, -448.f), 448.f));
        float q1 = (float)__nv_fp8_e4m3(fminf(fmaxf(n1 * s, -448.f), 448.f));
        float q2 = (float)__nv_fp8_e4m3(fminf(fmaxf(n2 * s, -448.f), 448.f));
        float q3 = (float)__nv_fp8_e4m3(fminf(fmaxf(n3 * s, -448.f), 448.f));
        __half2* ap = (__half2*)&g_A[base + (size_t)i * 4];
        ap[0] = __half2(__float2half_rn(q0), __float2half_rn(q1)); // exact: e4m3 subset of fp16
        ap[1] = __half2(__float2half_rn(q2), __float2half_rn(q3));
    }
    float wm = warp_max(am);
    if (lid == 0) red[wid] = wm;
    __syncthreads();
    if (threadIdx.x == 0) {
        float t = red[0];
        #pragma unroll
        for (int k = 1; k < 8; k++) t = fmaxf(t, red[k]);
        atomicMax(amax_u, __float_as_uint(t)); // all values >= 0: uint order == float order
    }
}

// ---------------- GEMM: out[M,N] = A[M,K] @ W[N,K]^T  (mma.sync fp16, fp32 accum) ----------------
// CTA tile: 128x128, BK=64, 256 threads (8 warps as 2x4, warp tile 64x32),
// 3-stage cp.async, 2 CTAs/SM (96KB smem, <=128 regs) to hide sync bubbles.
#define BM 128
#define BN 128
#define BK 64
#define GSTAGES 3
#define A_BYTES (BM * 128)                  // 16384
#define W_OFFB  A_BYTES
#define STAGE_BYTES (A_BYTES + BN * 128)    // 32768
#define SMEM_TOTAL (GSTAGES * STAGE_BYTES)  // 98304
#define NITER (KDIM / BK)                   // 64

__device__ __forceinline__ void load_stage(uint32_t sb, int buf, int t, int m0, int n0, int tid) {
    uint32_t base = sb + buf * STAGE_BYTES;
    int kk0 = t * BK;
    #pragma unroll
    for (int i = 0; i < 8; i++) {
        int u = tid + i * 256;          // 0..2047 ; 0..1023 = A, 1024..2047 = W
        const __half* src;
        uint32_t dst;
        int v = u & 1023;
        int row = v >> 3, c = v & 7;
        if (u < 1024) {
            dst = base + sw128((uint32_t)((row << 7) | (c << 4)));
            src = g_A + (size_t)(m0 + row) * KDIM + kk0 + c * 8;
        } else {
            dst = base + W_OFFB + sw128((uint32_t)((row << 7) | (c << 4)));
            src = g_W + (size_t)(n0 + row) * KDIM + kk0 + c * 8;
        }
        cp_async16(dst, src);
    }
}

__global__ void __launch_bounds__(256, 2) gemm_kernel(
    const float* __restrict__ bias, const float* __restrict__ scale_p, float* __restrict__ out)
{
    extern __shared__ __align__(1024) char smem[];
    uint32_t sb = smem_u32(smem);
    int tid = threadIdx.x, wid = tid >> 5, lane = tid & 31;

    // tile rasterization with M-grouping for L2 reuse of W
    constexpr int PN = NDIM / BN, GM = 16;         // PN=32
    int pid = blockIdx.x;
    int group = pid / (GM * PN);
    int m_t = group * GM + (pid % GM);
    int n_t = (pid % (GM * PN)) / GM;
    int m0 = m_t * BM, n0 = n_t * BN;

    int wm0 = (wid & 1) * 64;   // warp rows [wm0, wm0+64)
    int wn0 = (wid >> 1) * 32;  // warp cols [wn0, wn0+32)

    int mi = lane >> 3;         // ldmatrix sub-matrix index 0..3
    int lr = lane & 7;          // row within 8x8

    float acc[4][4][4];
    #pragma unroll
    for (int a = 0; a < 4; a++)
        #pragma unroll
        for (int b = 0; b < 4; b++)
            #pragma unroll
            for (int c = 0; c < 4; c++) acc[a][b][c] = 0.f;

    // prologue: prefetch stages 0,1
    #pragma unroll
    for (int t = 0; t < GSTAGES - 1; t++) {
        load_stage(sb, t, t, m0, n0, tid);
        asm volatile("cp.async.commit_group;" ::: "memory");
    }

    for (int s = 0; s < NITER; s++) {
        asm volatile("cp.async.wait_group 1;" ::: "memory");
        __syncthreads();

        int nt = s + GSTAGES - 1;
        if (nt < NITER) load_stage(sb, nt % GSTAGES, nt, m0, n0, tid);
        asm volatile("cp.async.commit_group;" ::: "memory");

        uint32_t buf = sb + (s % GSTAGES) * STAGE_BYTES;
        #pragma unroll
        for (int ks = 0; ks < 4; ks++) {
            int kk = ks * 16;
            // A fragments: 4 m16 tiles
            uint32_t aF[4][4];
            #pragma unroll
            for (int tm = 0; tm < 4; tm++) {
                int row = wm0 + tm * 16 + (mi & 1) * 8 + lr;
                int kc = kk + (mi >> 1) * 8;
                ldm_x4(aF[tm], buf + sw128((uint32_t)(row * 128 + kc * 2)));
            }
            // W fragments: 4 n8 tiles (two ldmatrix.x4)
            uint32_t bF[4][2];
            #pragma unroll
            for (int p = 0; p < 2; p++) {
                int nrow = wn0 + p * 16 + (mi >> 1) * 8 + lr;
                int kc = kk + (mi & 1) * 8;
                uint32_t r[4];
                ldm_x4(r, buf + W_OFFB + sw128((uint32_t)(nrow * 128 + kc * 2)));
                bF[2 * p][0] = r[0]; bF[2 * p][1] = r[1];
                bF[2 * p + 1][0] = r[2]; bF[2 * p + 1][1] = r[3];
            }
            #pragma unroll
            for (int tm = 0; tm < 4; tm++)
                #pragma unroll
                for (int tn = 0; tn < 4; tn++)
                    mma_f16(acc[tm][tn], aF[tm], bF[tn]);
        }
    }

    // ---- epilogue: scale by 1/s, add bias, write fp32 ----
    float inv_s = 1.0f / __ldg(scale_p);
    int g = lane >> 2;
    int c2 = (lane & 3) * 2;
    #pragma unroll
    for (int tm = 0; tm < 4; tm++) {
        #pragma unroll
        for (int tn = 0; tn < 4; tn++) {
            int m = m0 + wm0 + tm * 16 + g;
            int n = n0 + wn0 + tn * 8 + c2;
            float2 bv = *(const float2*)(bias + n);
            float2 o0, o1;
            o0.x = acc[tm][tn][0] * inv_s + bv.x;
            o0.y = acc[tm][tn][1] * inv_s + bv.y;
            o1.x = acc[tm][tn][2] * inv_s + bv.x;
            o1.y = acc[tm][tn][3] * inv_s + bv.y;
            *(float2*)(out + (size_t)m * NDIM + n) = o0;
            *(float2*)(out + (size_t)(m + 8) * NDIM + n) = o1;
        }
    }
}

// ---------------- launch ----------------
extern "C" void kernel_launch(void* const* d_in, const int* in_sizes, int n_in,
                              void* d_out, int out_size) {
    (void)in_sizes; (void)n_in; (void)out_size;
    const float* x     = (const float*)d_in[0];
    const float* res   = (const float*)d_in[1];
    const float* lw    = (const float*)d_in[2];
    const float* W     = (const float*)d_in[3];
    const float* bias  = (const float*)d_in[4];
    const float* scale = (const float*)d_in[5];

    float* out = (float*)d_out;
    float* res_out = out + (size_t)MDIM * NDIM;
    unsigned* amax_u = (unsigned*)(out + 2ull * (size_t)MDIM * NDIM);

    init_kernel<<<1, 32>>>(amax_u);
    convert_w_kernel<<<(NDIM * KDIM) / 1024, 256>>>(W);
    norm_kernel<<<MDIM, 256>>>(x, res, lw, scale, res_out, amax_u);

    cudaFuncSetAttribute(gemm_kernel, cudaFuncAttributeMaxDynamicSharedMemorySize, SMEM_TOTAL);
    gemm_kernel<<<(MDIM / BM) * (NDIM / BN), 256, SMEM_TOTAL>>>(bias, scale, out);
}

// round 5
// speedup vs baseline: 2.0643x; 1.0346x over previous
#include <cuda_runtime.h>
#include <cuda_fp16.h>
#include <cuda_fp8.h>
#include <cstdint>

// Problem dims (fixed by setup_inputs): B=4,S=2048 -> M=8192, H=K=4096, O=N=4096
#define MDIM 8192
#define KDIM 4096
#define NDIM 4096

// ---------------- scratch (static __device__, allocation-free) ----------------
__device__ __half g_A[(size_t)MDIM * KDIM];   // e4m3 values of norm*scale (exact in fp16)
__device__ __half g_W[(size_t)NDIM * KDIM];   // fp16 W

// ---------------- helpers ----------------
__device__ __forceinline__ uint32_t smem_u32(const void* p) {
    uint32_t a;
    asm("{ .reg .u64 t; cvta.to.shared.u64 t, %1; cvt.u32.u64 %0, t; }" : "=r"(a) : "l"(p));
    return a;
}
__device__ __forceinline__ void cp_async16(uint32_t dst, const void* src) {
    asm volatile("cp.async.cg.shared.global [%0], [%1], 16;"
                 :: "r"(dst), "l"(__cvta_generic_to_global(src)) : "memory");
}
__device__ __forceinline__ uint32_t sw128(uint32_t off) { return off ^ ((off >> 3) & 0x70); }

__device__ __forceinline__ void ldm_x4(uint32_t* r, uint32_t addr) {
    asm volatile("ldmatrix.sync.aligned.m8n8.x4.shared.b16 {%0,%1,%2,%3}, [%4];"
                 : "=r"(r[0]), "=r"(r[1]), "=r"(r[2]), "=r"(r[3]) : "r"(addr));
}
__device__ __forceinline__ void mma_f16(float* c, const uint32_t* a, const uint32_t* b) {
    asm volatile(
        "mma.sync.aligned.m16n8k16.row.col.f32.f16.f16.f32 "
        "{%0,%1,%2,%3}, {%4,%5,%6,%7}, {%8,%9}, {%0,%1,%2,%3};"
        : "+f"(c[0]), "+f"(c[1]), "+f"(c[2]), "+f"(c[3])
        : "r"(a[0]), "r"(a[1]), "r"(a[2]), "r"(a[3]), "r"(b[0]), "r"(b[1]));
}

// ---------------- prologue kernels ----------------
__global__ void init_kernel(unsigned* amax_u) {
    if (threadIdx.x == 0) *amax_u = 0u;
}

__global__ void __launch_bounds__(256) convert_w_kernel(const float* __restrict__ W) {
    size_t i = ((size_t)blockIdx.x * 256 + threadIdx.x) * 4;
    float4 w = *(const float4*)(W + i);
    __half2* hp = (__half2*)&g_W[i];
    hp[0] = __half2(__float2half_rn(w.x), __float2half_rn(w.y));
    hp[1] = __half2(__float2half_rn(w.z), __float2half_rn(w.w));
}

__device__ __forceinline__ float warp_sum(float v) {
    #pragma unroll
    for (int o = 16; o; o >>= 1) v += __shfl_xor_sync(0xFFFFFFFFu, v, o);
    return v;
}
__device__ __forceinline__ float warp_max(float v) {
    #pragma unroll
    for (int o = 16; o; o >>= 1) v = fmaxf(v, __shfl_xor_sync(0xFFFFFFFFu, v, o));
    return v;
}

// fused residual add + RMSNorm + fp8 quant (raw e4m3 value kept; 1/scale folded into epilogue)
__global__ void __launch_bounds__(256) norm_kernel(
    const float* __restrict__ x, const float* __restrict__ r,
    const float* __restrict__ lw, const float* __restrict__ scale_p,
    float* __restrict__ res_out, unsigned* __restrict__ amax_u)
{
    int row = blockIdx.x;
    size_t base = (size_t)row * KDIM;
    const float4* x4 = (const float4*)(x + base);
    const float4* r4 = (const float4*)(r + base);
    float4* ro4 = (float4*)(res_out + base);

    float4 v[4];
    float ss = 0.f;
    #pragma unroll
    for (int j = 0; j < 4; j++) {
        int i = threadIdx.x + j * 256;
        float4 a = x4[i];
        float4 bb = r4[i];
        a.x += bb.x; a.y += bb.y; a.z += bb.z; a.w += bb.w;
        v[j] = a;
        ro4[i] = a;
        ss += a.x * a.x + a.y * a.y + a.z * a.z + a.w * a.w;
    }
    __shared__ float red[8];
    __shared__ float bcast;
    int wid = threadIdx.x >> 5, lid = threadIdx.x & 31;
    float ws = warp_sum(ss);
    if (lid == 0) red[wid] = ws;
    __syncthreads();
    if (wid == 0) {
        float t = (lid < 8) ? red[lid] : 0.f;
        #pragma unroll
        for (int o = 4; o; o >>= 1) t += __shfl_xor_sync(0xFFFFFFFFu, t, o);
        if (lid == 0) bcast = t;
    }
    __syncthreads();
    float rstd = rsqrtf(bcast * (1.0f / KDIM) + 1e-5f);
    float s = __ldg(scale_p);

    float am = 0.f;
    const float4* w4 = (const float4*)lw;
    #pragma unroll
    for (int j = 0; j < 4; j++) {
        int i = threadIdx.x + j * 256;
        float4 wv = w4[i];
        float n0 = v[j].x * rstd * wv.x;
        float n1 = v[j].y * rstd * wv.y;
        float n2 = v[j].z * rstd * wv.z;
        float n3 = v[j].w * rstd * wv.w;
        am = fmaxf(am, fmaxf(fmaxf(fabsf(n0), fabsf(n1)), fmaxf(fabsf(n2), fabsf(n3))));
        float q0 = (float)__nv_fp8_e4m3(fminf(fmaxf(n0 * s, -448.f), 448.f));
        float q1 = (float)__nv_fp8_e4m3(fminf(fmaxf(n1 * s, -448.f), 448.f));
        float q2 = (float)__nv_fp8_e4m3(fminf(fmaxf(n2 * s, -448.f), 448.f));
        float q3 = (float)__nv_fp8_e4m3(fminf(fmaxf(n3 * s, -448.f), 448.f));
        __half2* ap = (__half2*)&g_A[base + (size_t)i * 4];
        ap[0] = __half2(__float2half_rn(q0), __float2half_rn(q1)); // exact: e4m3 subset of fp16
        ap[1] = __half2(__float2half_rn(q2), __float2half_rn(q3));
    }
    float wm = warp_max(am);
    if (lid == 0) red[wid] = wm;
    __syncthreads();
    if (threadIdx.x == 0) {
        float t = red[0];
        #pragma unroll
        for (int k = 1; k < 8; k++) t = fmaxf(t, red[k]);
        atomicMax(amax_u, __float_as_uint(t)); // all values >= 0: uint order == float order
    }
}

// ---------------- GEMM: out[M,N] = A[M,K] @ W[N,K]^T  (mma.sync fp16, fp32 accum) ----------------
// CTA tile: 128x128, BK=64, 128 threads (4 warps as 2x2, warp tile 64x64),
// 3-stage cp.async, 2 CTAs/SM. 64x64 warp tile cuts LDSM bytes/MAC by 1.5x
// (smem pipe was co-binding the tensor pipe at 64x32).
#define BM 128
#define BN 128
#define BK 64
#define GSTAGES 3
#define A_BYTES (BM * 128)                  // 16384
#define W_OFFB  A_BYTES
#define STAGE_BYTES (A_BYTES + BN * 128)    // 32768
#define SMEM_TOTAL (GSTAGES * STAGE_BYTES)  // 98304
#define NITER (KDIM / BK)                   // 64

__device__ __forceinline__ void load_stage(uint32_t sb, int buf, int t, int m0, int n0, int tid) {
    uint32_t base = sb + buf * STAGE_BYTES;
    int kk0 = t * BK;
    #pragma unroll
    for (int i = 0; i < 16; i++) {
        int u = tid + i * 128;          // 0..2047 ; 0..1023 = A, 1024..2047 = W
        const __half* src;
        uint32_t dst;
        int v = u & 1023;
        int row = v >> 3, c = v & 7;
        if (u < 1024) {
            dst = base + sw128((uint32_t)((row << 7) | (c << 4)));
            src = g_A + (size_t)(m0 + row) * KDIM + kk0 + c * 8;
        } else {
            dst = base + W_OFFB + sw128((uint32_t)((row << 7) | (c << 4)));
            src = g_W + (size_t)(n0 + row) * KDIM + kk0 + c * 8;
        }
        cp_async16(dst, src);
    }
}

__global__ void __launch_bounds__(128, 2) gemm_kernel(
    const float* __restrict__ bias, const float* __restrict__ scale_p, float* __restrict__ out)
{
    extern __shared__ __align__(1024) char smem[];
    uint32_t sb = smem_u32(smem);
    int tid = threadIdx.x, wid = tid >> 5, lane = tid & 31;

    // tile rasterization with M-grouping for L2 reuse of W
    constexpr int PN = NDIM / BN, GM = 16;         // PN=32
    int pid = blockIdx.x;
    int group = pid / (GM * PN);
    int m_t = group * GM + (pid % GM);
    int n_t = (pid % (GM * PN)) / GM;
    int m0 = m_t * BM, n0 = n_t * BN;

    int wm0 = (wid & 1) * 64;   // warp rows [wm0, wm0+64)
    int wn0 = (wid >> 1) * 64;  // warp cols [wn0, wn0+64)

    int mi = lane >> 3;         // ldmatrix sub-matrix index 0..3
    int lr = lane & 7;          // row within 8x8

    float acc[4][8][4];
    #pragma unroll
    for (int a = 0; a < 4; a++)
        #pragma unroll
        for (int b = 0; b < 8; b++)
            #pragma unroll
            for (int c = 0; c < 4; c++) acc[a][b][c] = 0.f;

    // prologue: prefetch stages 0,1
    #pragma unroll
    for (int t = 0; t < GSTAGES - 1; t++) {
        load_stage(sb, t, t, m0, n0, tid);
        asm volatile("cp.async.commit_group;" ::: "memory");
    }

    for (int s = 0; s < NITER; s++) {
        asm volatile("cp.async.wait_group 1;" ::: "memory");
        __syncthreads();

        int nt = s + GSTAGES - 1;
        if (nt < NITER) load_stage(sb, nt % GSTAGES, nt, m0, n0, tid);
        asm volatile("cp.async.commit_group;" ::: "memory");

        uint32_t buf = sb + (s % GSTAGES) * STAGE_BYTES;
        #pragma unroll
        for (int ks = 0; ks < 4; ks++) {
            int kk = ks * 16;
            // A fragments: 4 m16 tiles
            uint32_t aF[4][4];
            #pragma unroll
            for (int tm = 0; tm < 4; tm++) {
                int row = wm0 + tm * 16 + (mi & 1) * 8 + lr;
                int kc = kk + (mi >> 1) * 8;
                ldm_x4(aF[tm], buf + sw128((uint32_t)(row * 128 + kc * 2)));
            }
            // W fragments: 8 n8 tiles (four ldmatrix.x4)
            uint32_t bF[8][2];
            #pragma unroll
            for (int p = 0; p < 4; p++) {
                int nrow = wn0 + p * 16 + (mi >> 1) * 8 + lr;
                int kc = kk + (mi & 1) * 8;
                uint32_t r[4];
                ldm_x4(r, buf + W_OFFB + sw128((uint32_t)(nrow * 128 + kc * 2)));
                bF[2 * p][0] = r[0]; bF[2 * p][1] = r[1];
                bF[2 * p + 1][0] = r[2]; bF[2 * p + 1][1] = r[3];
            }
            #pragma unroll
            for (int tm = 0; tm < 4; tm++)
                #pragma unroll
                for (int tn = 0; tn < 8; tn++)
                    mma_f16(acc[tm][tn], aF[tm], bF[tn]);
        }
    }

    // ---- epilogue: scale by 1/s, add bias, write fp32 ----
    float inv_s = 1.0f / __ldg(scale_p);
    int g = lane >> 2;
    int c2 = (lane & 3) * 2;
    #pragma unroll
    for (int tm = 0; tm < 4; tm++) {
        #pragma unroll
        for (int tn = 0; tn < 8; tn++) {
            int m = m0 + wm0 + tm * 16 + g;
            int n = n0 + wn0 + tn * 8 + c2;
            float2 bv = *(const float2*)(bias + n);
            float2 o0, o1;
            o0.x = acc[tm][tn][0] * inv_s + bv.x;
            o0.y = acc[tm][tn][1] * inv_s + bv.y;
            o1.x = acc[tm][tn][2] * inv_s + bv.x;
            o1.y = acc[tm][tn][3] * inv_s + bv.y;
            *(float2*)(out + (size_t)m * NDIM + n) = o0;
            *(float2*)(out + (size_t)(m + 8) * NDIM + n) = o1;
        }
    }
}

// ---------------- launch ----------------
extern "C" void kernel_launch(void* const* d_in, const int* in_sizes, int n_in,
                              void* d_out, int out_size) {
    (void)in_sizes; (void)n_in; (void)out_size;
    const float* x     = (const float*)d_in[0];
    const float* res   = (const float*)d_in[1];
    const float* lw    = (const float*)d_in[2];
    const float* W     = (const float*)d_in[3];
    const float* bias  = (const float*)d_in[4];
    const float* scale = (const float*)d_in[5];

    float* out = (float*)d_out;
    float* res_out = out + (size_t)MDIM * NDIM;
    unsigned* amax_u = (unsigned*)(out + 2ull * (size_t)MDIM * NDIM);

    init_kernel<<<1, 32>>>(amax_u);
    convert_w_kernel<<<(NDIM * KDIM) / 1024, 256>>>(W);
    norm_kernel<<<MDIM, 256>>>(x, res, lw, scale, res_out, amax_u);

    cudaFuncSetAttribute(gemm_kernel, cudaFuncAttributeMaxDynamicSharedMemorySize, SMEM_TOTAL);
    gemm_kernel<<<(MDIM / BM) * (NDIM / BN), 128, SMEM_TOTAL>>>(bias, scale, out);
}